// round 1
// baseline (speedup 1.0000x reference)
#include <cuda_runtime.h>
#include <cstdint>

// Problem constants
#define BB 2
#define NN 2048            // N_P + N_S
#define NP 2000
#define NREL 8192
#define BNR (BB*NREL)      // 16384 relations total
#define NODES (BB*NN)      // 4096 node rows total
#define NF 128
#define IN_DIM 19
#define REL_DIM 56

// ---------------- scratch (device globals; no allocation allowed) ----------
__device__ float g_pin [NODES*IN_DIM];
__device__ float g_rin [BNR*REL_DIM];
__device__ float g_t0  [NODES*NF];
__device__ float g_t1  [NODES*NF];
__device__ float g_pEnc[NODES*NF];
__device__ float g_pEff[NODES*NF];
__device__ float g_r0  [BNR*NF];
__device__ float g_r1  [BNR*NF];
__device__ float g_relE[BNR*NF];
__device__ float g_agg [NODES*NF];
__device__ int   g_rr  [BNR];       // GLOBAL node index (b*NN + local)
__device__ int   g_rs  [BNR];

// ---------------- index extraction from one-hot Rr/Rs ----------------------
// warp per row; 2048 cols scanned as 16 float4 per lane
__global__ void extract_idx(const float* __restrict__ Rr,
                            const float* __restrict__ Rs,
                            int* __restrict__ rr, int* __restrict__ rs) {
    int gw   = (blockIdx.x * blockDim.x + threadIdx.x) >> 5;
    int lane = threadIdx.x & 31;
    if (gw >= 2 * BNR) return;
    const float* src = (gw < BNR) ? Rr : Rs;
    int row = (gw < BNR) ? gw : gw - BNR;
    const float4* p = reinterpret_cast<const float4*>(src + (size_t)row * NN);
    int found = -1;
#pragma unroll
    for (int i = 0; i < NN / 128; i++) {
        float4 v = p[i * 32 + lane];
        int base = i * 128 + lane * 4;
        if (v.x != 0.f) found = base;
        if (v.y != 0.f) found = base + 1;
        if (v.z != 0.f) found = base + 2;
        if (v.w != 0.f) found = base + 3;
    }
#pragma unroll
    for (int off = 16; off; off >>= 1)
        found = max(found, __shfl_xor_sync(0xffffffffu, found, off));
    if (lane == 0) {
        int b = row / NREL;
        ((gw < BNR) ? rr : rs)[row] = b * NN + found;  // store GLOBAL node idx
    }
}

// ---------------- build particle inputs [NODES, 19] ------------------------
// cols: attrs(0:2) | state_norm_t(2:14) | phys(14) | action(15:18) | den(18)
__global__ void build_pin(const float* __restrict__ state,
                          const float* __restrict__ attrs,
                          const float* __restrict__ action,
                          const float* __restrict__ pden,
                          const float* __restrict__ phys,
                          float* __restrict__ pin) {
    int i = blockIdx.x * blockDim.x + threadIdx.x;
    if (i >= NODES) return;
    int b = i / NN, n = i - b * NN;
    float* o = pin + (size_t)i * IN_DIM;
    o[0] = attrs[i * 2 + 0];
    o[1] = attrs[i * 2 + 1];
    float s[4][3];
#pragma unroll
    for (int t = 0; t < 4; t++)
#pragma unroll
        for (int k = 0; k < 3; k++)
            s[t][k] = state[((size_t)(b * 4 + t) * NN + n) * 3 + k];
#pragma unroll
    for (int t = 0; t < 3; t++)
#pragma unroll
        for (int k = 0; k < 3; k++)
            o[2 + t * 3 + k] = s[t + 1][k] - s[t][k];
#pragma unroll
    for (int k = 0; k < 3; k++) o[2 + 9 + k] = s[3][k];
    bool isP = (n < NP);
    o[14] = isP ? phys[b] : 0.f;
#pragma unroll
    for (int k = 0; k < 3; k++) o[15 + k] = action[(size_t)i * 3 + k];
    o[18] = isP ? pden[b] : 0.f;
}

// ---------------- build relation inputs [BNR, 56] --------------------------
// cols: p_r(0:19) | p_s(19:38) | a_r(38:40) | a_s(40:42) | gdiff(42)
//       | pos_diff(43:55) | dens_diff(55)
__global__ void build_rin(const float* __restrict__ pin,
                          const float* __restrict__ attrs,
                          const float* __restrict__ pinst,
                          const int* __restrict__ rr, const int* __restrict__ rs,
                          float* __restrict__ rin) {
    int r = blockIdx.x * blockDim.x + threadIdx.x;
    if (r >= BNR) return;
    int b  = r / NREL;
    int gr = rr[r], gs = rs[r];          // global node indices
    int ir = gr & (NN - 1), is_ = gs & (NN - 1);
    float* o = rin + (size_t)r * REL_DIM;
    const float* pr = pin + (size_t)gr * IN_DIM;
    const float* ps = pin + (size_t)gs * IN_DIM;
#pragma unroll
    for (int k = 0; k < IN_DIM; k++) o[k] = pr[k];
#pragma unroll
    for (int k = 0; k < IN_DIM; k++) o[19 + k] = ps[k];
    o[38] = attrs[gr * 2 + 0]; o[39] = attrs[gr * 2 + 1];
    o[40] = attrs[gs * 2 + 0]; o[41] = attrs[gs * 2 + 1];
    float gd = 0.f;
#pragma unroll
    for (int j = 0; j < 8; j++) {
        float a = (ir < NP) ? pinst[((size_t)b * NP + ir) * 8 + j] : 0.f;
        float c = (is_ < NP) ? pinst[((size_t)b * NP + is_) * 8 + j] : 0.f;
        gd += fabsf(a - c);
    }
    o[42] = gd;
#pragma unroll
    for (int k = 0; k < 12; k++) o[43 + k] = pr[2 + k] - ps[2 + k];
    o[55] = pr[18] - ps[18];
}

// ---------------- zero kernel ----------------------------------------------
__global__ void zero_k(float* __restrict__ p, int n) {
    int i = blockIdx.x * blockDim.x + threadIdx.x;
    if (i < n) p[i] = 0.f;
}

// ---------------- generic fused GEMM  C = epi(A@W + b) ---------------------
// BM=64 rows/block, N=128 cols (full), BK=16, 256 threads, 8x4 microtile.
// MODE 0: dense A [M,K]; epi = relu; write C (and C2 if non-null)
// MODE 1: relation propagator: A = [relE | pEff[rr] | pEff[rs]] (K=384);
//         epi = relu then atomicAdd-scatter into agg[rr]
// MODE 2: particle propagator: A = [pEnc | agg] (K=256);
//         epi = relu(acc + b + resid[row]); write C (resid==C ok)
template <int MODE>
__global__ void __launch_bounds__(256)
gemm_k(const float* __restrict__ A, const float* __restrict__ W,
       const float* __restrict__ bias,
       float* __restrict__ C, float* __restrict__ C2,
       int M, int K,
       const float* __restrict__ G1, const float* __restrict__ G2,
       const int* __restrict__ idxR, const int* __restrict__ idxS,
       float* __restrict__ agg) {
    __shared__ float As[16 * 65];
    __shared__ float Ws[16 * 128];
    int tid = threadIdx.x;
    int tx = tid & 31;         // col group: cols tx*4..tx*4+3
    int ty = tid >> 5;         // row group: rows ty*8..ty*8+7
    int rowBase = blockIdx.x * 64;

    float acc[8][4];
#pragma unroll
    for (int i = 0; i < 8; i++)
#pragma unroll
        for (int j = 0; j < 4; j++) acc[i][j] = 0.f;

    int lm  = tid >> 2;        // A-load row 0..63
    int lk0 = (tid & 3) * 4;   // A-load k-offset 0,4,8,12
    int wk  = tid >> 4;        // W-load k-row 0..15
    int wc  = (tid & 15) * 8;  // W-load col base

    for (int k0 = 0; k0 < K; k0 += 16) {
        {   // load W tile (16 x 128)
            int kk = k0 + wk;
            const float* wp = W + (size_t)kk * 128 + wc;
            bool ok = (kk < K);
#pragma unroll
            for (int j = 0; j < 8; j++)
                Ws[wk * 128 + wc + j] = ok ? wp[j] : 0.f;
        }
        {   // load A tile (64 x 16), possibly gathered
            int grow = rowBase + lm;
#pragma unroll
            for (int j = 0; j < 4; j++) {
                int kk = lk0 + j;
                int kg = k0 + kk;
                float v = 0.f;
                if (grow < M && kg < K) {
                    if (MODE == 0) {
                        v = A[(size_t)grow * K + kg];
                    } else if (MODE == 1) {
                        if (kg < 128)      v = G1[(size_t)grow * 128 + kg];
                        else if (kg < 256) v = G2[(size_t)idxR[grow] * 128 + (kg - 128)];
                        else               v = G2[(size_t)idxS[grow] * 128 + (kg - 256)];
                    } else {
                        if (kg < 128) v = G1[(size_t)grow * 128 + kg];
                        else          v = G2[(size_t)grow * 128 + (kg - 128)];
                    }
                }
                As[kk * 65 + lm] = v;
            }
        }
        __syncthreads();
#pragma unroll
        for (int kk = 0; kk < 16; kk++) {
            float4 wv = *reinterpret_cast<const float4*>(&Ws[kk * 128 + tx * 4]);
#pragma unroll
            for (int i = 0; i < 8; i++) {
                float a = As[kk * 65 + ty * 8 + i];
                acc[i][0] += a * wv.x;
                acc[i][1] += a * wv.y;
                acc[i][2] += a * wv.z;
                acc[i][3] += a * wv.w;
            }
        }
        __syncthreads();
    }

    float4 bv = *reinterpret_cast<const float4*>(&bias[tx * 4]);
#pragma unroll
    for (int i = 0; i < 8; i++) {
        int grow = rowBase + ty * 8 + i;
        if (grow >= M) continue;
        if (MODE == 1) {
            int node = idxR[grow];
            float* dst = agg + (size_t)node * 128 + tx * 4;
            atomicAdd(dst + 0, fmaxf(acc[i][0] + bv.x, 0.f));
            atomicAdd(dst + 1, fmaxf(acc[i][1] + bv.y, 0.f));
            atomicAdd(dst + 2, fmaxf(acc[i][2] + bv.z, 0.f));
            atomicAdd(dst + 3, fmaxf(acc[i][3] + bv.w, 0.f));
        } else if (MODE == 2) {
            size_t o = (size_t)grow * 128 + tx * 4;
            float4 r = *reinterpret_cast<const float4*>(&C2[o]);
            float4 out;
            out.x = fmaxf(acc[i][0] + bv.x + r.x, 0.f);
            out.y = fmaxf(acc[i][1] + bv.y + r.y, 0.f);
            out.z = fmaxf(acc[i][2] + bv.z + r.z, 0.f);
            out.w = fmaxf(acc[i][3] + bv.w + r.w, 0.f);
            *reinterpret_cast<float4*>(&C[o]) = out;
        } else {
            size_t o = (size_t)grow * 128 + tx * 4;
            float4 out;
            out.x = fmaxf(acc[i][0] + bv.x, 0.f);
            out.y = fmaxf(acc[i][1] + bv.y, 0.f);
            out.z = fmaxf(acc[i][2] + bv.z, 0.f);
            out.w = fmaxf(acc[i][3] + bv.w, 0.f);
            *reinterpret_cast<float4*>(&C[o]) = out;
            if (C2) *reinterpret_cast<float4*>(&C2[o]) = out;
        }
    }
}

// ---------------- final: motion head (N=3) + clamp + add last pos ----------
__global__ void final_k(const float* __restrict__ h,
                        const float* __restrict__ W2,
                        const float* __restrict__ b2,
                        const float* __restrict__ state,
                        float* __restrict__ out) {
    int gw   = (blockIdx.x * blockDim.x + threadIdx.x) >> 5;
    int lane = threadIdx.x & 31;
    if (gw >= BB * NP) return;
    int b = gw / NP, n = gw - b * NP;
    const float* hr = h + ((size_t)b * NN + n) * 128;
    float hv[4];
#pragma unroll
    for (int j = 0; j < 4; j++) hv[j] = hr[lane + 32 * j];
#pragma unroll
    for (int k = 0; k < 3; k++) {
        float s = 0.f;
#pragma unroll
        for (int j = 0; j < 4; j++) s += hv[j] * W2[(lane + 32 * j) * 3 + k];
#pragma unroll
        for (int off = 16; off; off >>= 1) s += __shfl_xor_sync(0xffffffffu, s, off);
        if (lane == 0) {
            float m = fminf(fmaxf(s + b2[k], -100.f), 100.f);
            out[(size_t)gw * 3 + k] =
                state[((size_t)(b * 4 + 3) * NN + n) * 3 + k] + m;
        }
    }
}

// ---------------------------------------------------------------------------
extern "C" void kernel_launch(void* const* d_in, const int* in_sizes, int n_in,
                              void* d_out, int out_size) {
    const float* state  = (const float*)d_in[0];
    const float* attrs  = (const float*)d_in[1];
    const float* Rr     = (const float*)d_in[2];
    const float* Rs     = (const float*)d_in[3];
    const float* pinst  = (const float*)d_in[4];
    const float* action = (const float*)d_in[5];
    const float* pden   = (const float*)d_in[6];
    const float* phys   = (const float*)d_in[7];
    const float* pe_W0 = (const float*)d_in[8],  *pe_b0 = (const float*)d_in[9];
    const float* pe_W1 = (const float*)d_in[10], *pe_b1 = (const float*)d_in[11];
    const float* pe_W2 = (const float*)d_in[12], *pe_b2 = (const float*)d_in[13];
    const float* re_W0 = (const float*)d_in[14], *re_b0 = (const float*)d_in[15];
    const float* re_W1 = (const float*)d_in[16], *re_b1 = (const float*)d_in[17];
    const float* re_W2 = (const float*)d_in[18], *re_b2 = (const float*)d_in[19];
    const float* pp_W  = (const float*)d_in[20], *pp_b  = (const float*)d_in[21];
    const float* rp_W  = (const float*)d_in[22], *rp_b  = (const float*)d_in[23];
    const float* np_W0 = (const float*)d_in[24], *np_b0 = (const float*)d_in[25];
    const float* np_W1 = (const float*)d_in[26], *np_b1 = (const float*)d_in[27];
    const float* np_W2 = (const float*)d_in[28], *np_b2 = (const float*)d_in[29];
    float* out = (float*)d_out;

    float *pin, *rin, *t0, *t1, *pEnc, *pEff, *r0, *r1, *relE, *agg;
    int *rr, *rs;
    cudaGetSymbolAddress((void**)&pin,  g_pin);
    cudaGetSymbolAddress((void**)&rin,  g_rin);
    cudaGetSymbolAddress((void**)&t0,   g_t0);
    cudaGetSymbolAddress((void**)&t1,   g_t1);
    cudaGetSymbolAddress((void**)&pEnc, g_pEnc);
    cudaGetSymbolAddress((void**)&pEff, g_pEff);
    cudaGetSymbolAddress((void**)&r0,   g_r0);
    cudaGetSymbolAddress((void**)&r1,   g_r1);
    cudaGetSymbolAddress((void**)&relE, g_relE);
    cudaGetSymbolAddress((void**)&agg,  g_agg);
    cudaGetSymbolAddress((void**)&rr,   g_rr);
    cudaGetSymbolAddress((void**)&rs,   g_rs);

    // 1) edge indices from one-hot Rr/Rs
    extract_idx<<<(2 * BNR * 32 + 255) / 256, 256>>>(Rr, Rs, rr, rs);

    // 2) node + relation feature assembly
    build_pin<<<(NODES + 255) / 256, 256>>>(state, attrs, action, pden, phys, pin);
    build_rin<<<(BNR + 127) / 128, 128>>>(pin, attrs, pinst, rr, rs, rin);

    // 3) particle encoder (19->128->128->128), copy last into particle_effect
    gemm_k<0><<<NODES / 64, 256>>>(pin, pe_W0, pe_b0, t0, nullptr, NODES, IN_DIM,
                                   nullptr, nullptr, nullptr, nullptr, nullptr);
    gemm_k<0><<<NODES / 64, 256>>>(t0, pe_W1, pe_b1, t1, nullptr, NODES, NF,
                                   nullptr, nullptr, nullptr, nullptr, nullptr);
    gemm_k<0><<<NODES / 64, 256>>>(t1, pe_W2, pe_b2, pEnc, pEff, NODES, NF,
                                   nullptr, nullptr, nullptr, nullptr, nullptr);

    // 4) relation encoder (56->128->128->128)
    gemm_k<0><<<BNR / 64, 256>>>(rin, re_W0, re_b0, r0, nullptr, BNR, REL_DIM,
                                 nullptr, nullptr, nullptr, nullptr, nullptr);
    gemm_k<0><<<BNR / 64, 256>>>(r0, re_W1, re_b1, r1, nullptr, BNR, NF,
                                 nullptr, nullptr, nullptr, nullptr, nullptr);
    gemm_k<0><<<BNR / 64, 256>>>(r1, re_W2, re_b2, relE, nullptr, BNR, NF,
                                 nullptr, nullptr, nullptr, nullptr, nullptr);

    // 5) propagation: 3 steps
    for (int step = 0; step < 3; step++) {
        zero_k<<<(NODES * NF + 255) / 256, 256>>>(agg, NODES * NF);
        // relation propagator + fused scatter-add into agg
        gemm_k<1><<<BNR / 64, 256>>>(nullptr, rp_W, rp_b, nullptr, nullptr,
                                     BNR, 3 * NF, relE, pEff, rr, rs, agg);
        // particle propagator with residual, in-place on pEff
        gemm_k<2><<<NODES / 64, 256>>>(nullptr, pp_W, pp_b, pEff, pEff,
                                       NODES, 2 * NF, pEnc, agg,
                                       nullptr, nullptr, nullptr);
    }

    // 6) non-rigid predictor head
    gemm_k<0><<<NODES / 64, 256>>>(pEff, np_W0, np_b0, t0, nullptr, NODES, NF,
                                   nullptr, nullptr, nullptr, nullptr, nullptr);
    gemm_k<0><<<NODES / 64, 256>>>(t0, np_W1, np_b1, t1, nullptr, NODES, NF,
                                   nullptr, nullptr, nullptr, nullptr, nullptr);
    final_k<<<(BB * NP * 32 + 255) / 256, 256>>>(t1, np_W2, np_b2, state, out);
}

// round 2
// speedup vs baseline: 2.3288x; 2.3288x over previous
#include <cuda_runtime.h>
#include <cuda_bf16.h>
#include <mma.h>
#include <cstdint>

using namespace nvcuda;

// Problem constants
#define BB 2
#define NN 2048
#define NP 2000
#define NREL 8192
#define BNR (BB*NREL)      // 16384
#define NODES (BB*NN)      // 4096
#define NF 128
#define CS_LD 132

// ---------------- scratch ---------------------------------------------------
__device__ float          g_pin_f[NODES*19];
__device__ __nv_bfloat16  g_pin_h[NODES*32];       // padded K=32
__device__ __nv_bfloat16  g_rin_h[BNR*64];         // padded K=64
__device__ __nv_bfloat16  g_t0 [NODES*NF];
__device__ __nv_bfloat16  g_t1 [NODES*NF];
__device__ __nv_bfloat16  g_pEnc[NODES*NF];
__device__ __nv_bfloat16  g_pEff[NODES*NF];
__device__ __nv_bfloat16  g_r0 [BNR*NF];
__device__ __nv_bfloat16  g_r1 [BNR*NF];
__device__ __nv_bfloat16  g_relE[BNR*NF];
__device__ float          g_agg[NODES*NF];
__device__ int            g_rr[BNR];
__device__ int            g_rs[BNR];
__device__ __nv_bfloat16  g_wbuf[1504*128];        // all converted weights

// weight row offsets inside g_wbuf
#define WO_PE0 0
#define WO_PE1 32
#define WO_PE2 160
#define WO_RE0 288
#define WO_RE1 352
#define WO_RE2 480
#define WO_PP  608
#define WO_RP  864
#define WO_NP0 1248
#define WO_NP1 1376
#define W_TOTAL_ROWS 1504

// ---------------- helpers ---------------------------------------------------
__device__ __forceinline__ uint32_t pack_bf2(float a, float b) {
    __nv_bfloat162 h = __floats2bfloat162_rn(a, b);
    return *reinterpret_cast<uint32_t*>(&h);
}
__device__ __forceinline__ float2 unpack_bf2(uint32_t u) {
    __nv_bfloat162 h = *reinterpret_cast<__nv_bfloat162*>(&u);
    return make_float2(__bfloat162float(h.x), __bfloat162float(h.y));
}

// ---------------- weight conversion fp32 -> bf16 (zero-padded rows) ---------
struct WConvArgs {
    const float* src[10];
    int rowStart[10];
    int srcRows[10];
};
__global__ void convert_w(WConvArgs a, __nv_bfloat16* __restrict__ wbuf) {
    int row = blockIdx.x, col = threadIdx.x;
    int seg = 0;
#pragma unroll
    for (int i = 1; i < 10; i++) if (row >= a.rowStart[i]) seg = i;
    int r = row - a.rowStart[seg];
    float v = (r < a.srcRows[seg]) ? a.src[seg][r * 128 + col] : 0.f;
    wbuf[row * 128 + col] = __float2bfloat16(v);
}

// ---------------- index extraction from one-hot Rr/Rs -----------------------
__global__ void extract_idx(const float* __restrict__ Rr,
                            const float* __restrict__ Rs,
                            int* __restrict__ rr, int* __restrict__ rs) {
    int gw   = (blockIdx.x * blockDim.x + threadIdx.x) >> 5;
    int lane = threadIdx.x & 31;
    if (gw >= 2 * BNR) return;
    const float* src = (gw < BNR) ? Rr : Rs;
    int row = (gw < BNR) ? gw : gw - BNR;
    const float4* p = reinterpret_cast<const float4*>(src + (size_t)row * NN);
    int found = -1;
#pragma unroll
    for (int i = 0; i < NN / 128; i++) {
        float4 v = p[i * 32 + lane];
        int base = i * 128 + lane * 4;
        if (v.x != 0.f) found = base;
        if (v.y != 0.f) found = base + 1;
        if (v.z != 0.f) found = base + 2;
        if (v.w != 0.f) found = base + 3;
    }
#pragma unroll
    for (int off = 16; off; off >>= 1)
        found = max(found, __shfl_xor_sync(0xffffffffu, found, off));
    if (lane == 0) {
        int b = row / NREL;
        ((gw < BNR) ? rr : rs)[row] = b * NN + found;
    }
}

// ---------------- build particle inputs -------------------------------------
// fp32 copy [NODES,19] for rel assembly + bf16 padded [NODES,32] for GEMM
__global__ void build_pin(const float* __restrict__ state,
                          const float* __restrict__ attrs,
                          const float* __restrict__ action,
                          const float* __restrict__ pden,
                          const float* __restrict__ phys,
                          float* __restrict__ pf,
                          __nv_bfloat16* __restrict__ ph) {
    int i = blockIdx.x * blockDim.x + threadIdx.x;
    if (i >= NODES) return;
    int b = i / NN, n = i - b * NN;
    float o[19];
    o[0] = attrs[i * 2 + 0];
    o[1] = attrs[i * 2 + 1];
    float s[4][3];
#pragma unroll
    for (int t = 0; t < 4; t++)
#pragma unroll
        for (int k = 0; k < 3; k++)
            s[t][k] = state[((size_t)(b * 4 + t) * NN + n) * 3 + k];
#pragma unroll
    for (int t = 0; t < 3; t++)
#pragma unroll
        for (int k = 0; k < 3; k++)
            o[2 + t * 3 + k] = s[t + 1][k] - s[t][k];
#pragma unroll
    for (int k = 0; k < 3; k++) o[11 + k] = s[3][k];
    bool isP = (n < NP);
    o[14] = isP ? phys[b] : 0.f;
#pragma unroll
    for (int k = 0; k < 3; k++) o[15 + k] = action[(size_t)i * 3 + k];
    o[18] = isP ? pden[b] : 0.f;
#pragma unroll
    for (int k = 0; k < 19; k++) pf[(size_t)i * 19 + k] = o[k];
#pragma unroll
    for (int k = 0; k < 19; k++) ph[(size_t)i * 32 + k] = __float2bfloat16(o[k]);
#pragma unroll
    for (int k = 19; k < 32; k++) ph[(size_t)i * 32 + k] = __float2bfloat16(0.f);
}

// ---------------- build relation inputs bf16 [BNR,64] (56 + zero pad) -------
__global__ void build_rin(const float* __restrict__ pf,
                          const float* __restrict__ attrs,
                          const float* __restrict__ pinst,
                          const int* __restrict__ rr, const int* __restrict__ rs,
                          __nv_bfloat16* __restrict__ rin) {
    int r = blockIdx.x * blockDim.x + threadIdx.x;
    if (r >= BNR) return;
    int b  = r / NREL;
    int gr = rr[r], gs = rs[r];
    int ir = gr & (NN - 1), is_ = gs & (NN - 1);
    float o[56];
    const float* pr = pf + (size_t)gr * 19;
    const float* ps = pf + (size_t)gs * 19;
#pragma unroll
    for (int k = 0; k < 19; k++) o[k] = pr[k];
#pragma unroll
    for (int k = 0; k < 19; k++) o[19 + k] = ps[k];
    o[38] = attrs[gr * 2 + 0]; o[39] = attrs[gr * 2 + 1];
    o[40] = attrs[gs * 2 + 0]; o[41] = attrs[gs * 2 + 1];
    float gd = 0.f;
#pragma unroll
    for (int j = 0; j < 8; j++) {
        float a = (ir < NP) ? pinst[((size_t)b * NP + ir) * 8 + j] : 0.f;
        float c = (is_ < NP) ? pinst[((size_t)b * NP + is_) * 8 + j] : 0.f;
        gd += fabsf(a - c);
    }
    o[42] = gd;
#pragma unroll
    for (int k = 0; k < 12; k++) o[43 + k] = pr[2 + k] - ps[2 + k];
    o[55] = pr[18] - ps[18];
    __nv_bfloat16* dst = rin + (size_t)r * 64;
#pragma unroll
    for (int k = 0; k < 56; k++) dst[k] = __float2bfloat16(o[k]);
#pragma unroll
    for (int k = 56; k < 64; k++) dst[k] = __float2bfloat16(0.f);
}

// ---------------- shared-memory layout for wmma GEMM ------------------------
struct SmemT {
    union {
        struct {
            __nv_bfloat16 As[64 * 24];    // [64][24], K-tile stride 24
            __nv_bfloat16 Ws[16 * 136];   // [16][136]
        } s;
        float Cs[64 * CS_LD];             // epilogue staging
    } u;
    int idx[128];                          // MODE1: rr (0..63), rs (64..127)
};

// ---------------- wmma GEMM body: C = epi(A @ W + bias) ---------------------
// BM=64, BN=128, BK=16, 256 threads (8 warps: 4 along M, 2 along N).
// MODE 0: dense A (lda); write bf16 C (+C2 dup); optional zero of agg rows.
// MODE 1: A = [relE(A) | G2[idxR] | G2[idxS]], K=384; relu -> atomicAdd agg[idxR].
// MODE 2: A = [pEnc(A) | aggIn(f32)], K=256; relu(acc+bias+C[row]) -> C; zero agg.
template <int MODE>
__device__ __forceinline__ void gemm_body(
    SmemT& sm,
    const __nv_bfloat16* __restrict__ A, int lda,
    const __nv_bfloat16* __restrict__ G2,
    const float* __restrict__ aggIn,
    const __nv_bfloat16* __restrict__ W,
    const float* __restrict__ bias,
    __nv_bfloat16* __restrict__ C,
    __nv_bfloat16* __restrict__ C2,
    float* __restrict__ agg,
    const int* __restrict__ idxR,
    const int* __restrict__ idxS,
    int K, int rowBase)
{
    const int tid = threadIdx.x;
    const int wid = tid >> 5;
    const int wm = wid & 3;        // warp row 0..3  (16 rows each)
    const int wn = wid >> 2;       // warp col 0..1  (64 cols each)

    if (MODE == 1) {
        if (tid < 64)       sm.idx[tid] = idxR[rowBase + tid];
        else if (tid < 128) sm.idx[tid] = idxS[rowBase + tid - 64];
    }
    __syncthreads();

    wmma::fragment<wmma::accumulator, 16, 16, 16, float> acc[4];
#pragma unroll
    for (int nf = 0; nf < 4; nf++) wmma::fill_fragment(acc[nf], 0.f);

    const int ar = tid >> 2;            // A stage row 0..63
    const int ak = (tid & 3) * 4;       // A stage k offset 0,4,8,12
    const int grow = rowBase + ar;
    const int wr = tid >> 4;            // W stage row 0..15
    const int wc = (tid & 15) * 8;      // W stage col

    for (int k0 = 0; k0 < K; k0 += 16) {
        // stage A tile (64 x 16) bf16, with gathers per MODE
        uint2 av;
        int kg = k0 + ak;
        if (MODE == 0) {
            av = *reinterpret_cast<const uint2*>(A + (size_t)grow * lda + kg);
        } else if (MODE == 1) {
            const __nv_bfloat16* p;
            if (kg < 128)      p = A  + (size_t)grow * 128 + kg;
            else if (kg < 256) p = G2 + (size_t)sm.idx[ar] * 128 + (kg - 128);
            else               p = G2 + (size_t)sm.idx[64 + ar] * 128 + (kg - 256);
            av = *reinterpret_cast<const uint2*>(p);
        } else {
            if (kg < 128) {
                av = *reinterpret_cast<const uint2*>(A + (size_t)grow * 128 + kg);
            } else {
                float4 f = *reinterpret_cast<const float4*>(
                    aggIn + (size_t)grow * 128 + (kg - 128));
                av.x = pack_bf2(f.x, f.y);
                av.y = pack_bf2(f.z, f.w);
            }
        }
        *reinterpret_cast<uint2*>(&sm.u.s.As[ar * 24 + ak]) = av;
        // stage W tile (16 x 128) bf16
        *reinterpret_cast<uint4*>(&sm.u.s.Ws[wr * 136 + wc]) =
            *reinterpret_cast<const uint4*>(W + (size_t)(k0 + wr) * 128 + wc);
        __syncthreads();

        wmma::fragment<wmma::matrix_a, 16, 16, 16, __nv_bfloat16, wmma::row_major> af;
        wmma::load_matrix_sync(af, &sm.u.s.As[wm * 16 * 24], 24);
#pragma unroll
        for (int nf = 0; nf < 4; nf++) {
            wmma::fragment<wmma::matrix_b, 16, 16, 16, __nv_bfloat16, wmma::row_major> bf;
            wmma::load_matrix_sync(bf, &sm.u.s.Ws[wn * 64 + nf * 16], 136);
            wmma::mma_sync(acc[nf], af, bf, acc[nf]);
        }
        __syncthreads();
    }

    // epilogue: stage accumulators to smem fp32, then apply epi per element
#pragma unroll
    for (int nf = 0; nf < 4; nf++)
        wmma::store_matrix_sync(&sm.u.Cs[(wm * 16) * CS_LD + wn * 64 + nf * 16],
                                acc[nf], CS_LD, wmma::mem_row_major);
    __syncthreads();

#pragma unroll
    for (int it = 0; it < 8; it++) {
        int e = tid + it * 256;            // quad index 0..2047
        int row = e >> 5;
        int c4  = (e & 31) * 4;
        int gr2 = rowBase + row;
        float4 v = *reinterpret_cast<float4*>(&sm.u.Cs[row * CS_LD + c4]);
        float4 b = *reinterpret_cast<const float4*>(&bias[c4]);
        v.x += b.x; v.y += b.y; v.z += b.z; v.w += b.w;
        if (MODE == 2) {
            uint2 rv = *reinterpret_cast<const uint2*>(C + (size_t)gr2 * 128 + c4);
            float2 r0 = unpack_bf2(rv.x), r1 = unpack_bf2(rv.y);
            v.x += r0.x; v.y += r0.y; v.z += r1.x; v.w += r1.y;
        }
        v.x = fmaxf(v.x, 0.f); v.y = fmaxf(v.y, 0.f);
        v.z = fmaxf(v.z, 0.f); v.w = fmaxf(v.w, 0.f);
        if (MODE == 1) {
            float* dst = agg + (size_t)sm.idx[row] * 128 + c4;
            atomicAdd(dst + 0, v.x);
            atomicAdd(dst + 1, v.y);
            atomicAdd(dst + 2, v.z);
            atomicAdd(dst + 3, v.w);
        } else {
            uint2 o;
            o.x = pack_bf2(v.x, v.y);
            o.y = pack_bf2(v.z, v.w);
            *reinterpret_cast<uint2*>(&C[(size_t)gr2 * 128 + c4]) = o;
            if (MODE == 0 && C2)
                *reinterpret_cast<uint2*>(&C2[(size_t)gr2 * 128 + c4]) = o;
            if (agg)
                *reinterpret_cast<float4*>(&agg[(size_t)gr2 * 128 + c4]) =
                    make_float4(0.f, 0.f, 0.f, 0.f);
        }
    }
}

// ---------------- kernel wrappers -------------------------------------------
// Dual-segment MODE0 (fills the chip by fusing particle+relation layers)
__global__ void __launch_bounds__(256) enc_k(
    const __nv_bfloat16* A1, int lda1, int K1, const __nv_bfloat16* W1,
    const float* b1, __nv_bfloat16* C1, __nv_bfloat16* C1b, float* agg1, int nb1,
    const __nv_bfloat16* A2, int lda2, int K2, const __nv_bfloat16* W2,
    const float* b2, __nv_bfloat16* C2o)
{
    __shared__ SmemT sm;
    int bx = blockIdx.x;
    if (bx < nb1)
        gemm_body<0>(sm, A1, lda1, nullptr, nullptr, W1, b1, C1, C1b, agg1,
                     nullptr, nullptr, K1, bx * 64);
    else
        gemm_body<0>(sm, A2, lda2, nullptr, nullptr, W2, b2, C2o, nullptr, nullptr,
                     nullptr, nullptr, K2, (bx - nb1) * 64);
}

__global__ void __launch_bounds__(256) relprop_k(
    const __nv_bfloat16* relE, const __nv_bfloat16* pEff,
    const __nv_bfloat16* W, const float* bias, float* agg,
    const int* rr, const int* rs)
{
    __shared__ SmemT sm;
    gemm_body<1>(sm, relE, 128, pEff, nullptr, W, bias, nullptr, nullptr, agg,
                 rr, rs, 384, blockIdx.x * 64);
}

__global__ void __launch_bounds__(256) partprop_k(
    const __nv_bfloat16* pEnc, const float* aggIn,
    const __nv_bfloat16* W, const float* bias, __nv_bfloat16* pEff, float* aggZ)
{
    __shared__ SmemT sm;
    gemm_body<2>(sm, pEnc, 128, nullptr, aggIn, W, bias, pEff, nullptr, aggZ,
                 nullptr, nullptr, 256, blockIdx.x * 64);
}

// ---------------- final: motion head (N=3) + clamp + add last pos -----------
__global__ void final_k(const __nv_bfloat16* __restrict__ h,
                        const float* __restrict__ W2,
                        const float* __restrict__ b2,
                        const float* __restrict__ state,
                        float* __restrict__ out) {
    int gw   = (blockIdx.x * blockDim.x + threadIdx.x) >> 5;
    int lane = threadIdx.x & 31;
    if (gw >= BB * NP) return;
    int b = gw / NP, n = gw - b * NP;
    const __nv_bfloat16* hr = h + ((size_t)b * NN + n) * 128;
    float hv[4];
#pragma unroll
    for (int j = 0; j < 4; j++) hv[j] = __bfloat162float(hr[lane + 32 * j]);
#pragma unroll
    for (int k = 0; k < 3; k++) {
        float s = 0.f;
#pragma unroll
        for (int j = 0; j < 4; j++) s += hv[j] * W2[(lane + 32 * j) * 3 + k];
#pragma unroll
        for (int off = 16; off; off >>= 1) s += __shfl_xor_sync(0xffffffffu, s, off);
        if (lane == 0) {
            float m = fminf(fmaxf(s + b2[k], -100.f), 100.f);
            out[(size_t)gw * 3 + k] =
                state[((size_t)(b * 4 + 3) * NN + n) * 3 + k] + m;
        }
    }
}

// ---------------------------------------------------------------------------
extern "C" void kernel_launch(void* const* d_in, const int* in_sizes, int n_in,
                              void* d_out, int out_size) {
    const float* state  = (const float*)d_in[0];
    const float* attrs  = (const float*)d_in[1];
    const float* Rr     = (const float*)d_in[2];
    const float* Rs     = (const float*)d_in[3];
    const float* pinst  = (const float*)d_in[4];
    const float* action = (const float*)d_in[5];
    const float* pden   = (const float*)d_in[6];
    const float* phys   = (const float*)d_in[7];
    const float* pe_W0 = (const float*)d_in[8],  *pe_b0 = (const float*)d_in[9];
    const float* pe_W1 = (const float*)d_in[10], *pe_b1 = (const float*)d_in[11];
    const float* pe_W2 = (const float*)d_in[12], *pe_b2 = (const float*)d_in[13];
    const float* re_W0 = (const float*)d_in[14], *re_b0 = (const float*)d_in[15];
    const float* re_W1 = (const float*)d_in[16], *re_b1 = (const float*)d_in[17];
    const float* re_W2 = (const float*)d_in[18], *re_b2 = (const float*)d_in[19];
    const float* pp_W  = (const float*)d_in[20], *pp_b  = (const float*)d_in[21];
    const float* rp_W  = (const float*)d_in[22], *rp_b  = (const float*)d_in[23];
    const float* np_W0 = (const float*)d_in[24], *np_b0 = (const float*)d_in[25];
    const float* np_W1 = (const float*)d_in[26], *np_b1 = (const float*)d_in[27];
    const float* np_W2 = (const float*)d_in[28], *np_b2 = (const float*)d_in[29];
    float* out = (float*)d_out;

    float *pin_f, *agg;
    __nv_bfloat16 *pin_h, *rin_h, *t0, *t1, *pEnc, *pEff, *r0, *r1, *relE, *wbuf;
    int *rr, *rs;
    cudaGetSymbolAddress((void**)&pin_f, g_pin_f);
    cudaGetSymbolAddress((void**)&pin_h, g_pin_h);
    cudaGetSymbolAddress((void**)&rin_h, g_rin_h);
    cudaGetSymbolAddress((void**)&t0,    g_t0);
    cudaGetSymbolAddress((void**)&t1,    g_t1);
    cudaGetSymbolAddress((void**)&pEnc,  g_pEnc);
    cudaGetSymbolAddress((void**)&pEff,  g_pEff);
    cudaGetSymbolAddress((void**)&r0,    g_r0);
    cudaGetSymbolAddress((void**)&r1,    g_r1);
    cudaGetSymbolAddress((void**)&relE,  g_relE);
    cudaGetSymbolAddress((void**)&agg,   g_agg);
    cudaGetSymbolAddress((void**)&rr,    g_rr);
    cudaGetSymbolAddress((void**)&rs,    g_rs);
    cudaGetSymbolAddress((void**)&wbuf,  g_wbuf);

    // 0) convert all weights to bf16 (zero-padded rows)
    WConvArgs wa;
    const float* srcs[10] = {pe_W0, pe_W1, pe_W2, re_W0, re_W1, re_W2,
                             pp_W, rp_W, np_W0, np_W1};
    const int starts[10]  = {WO_PE0, WO_PE1, WO_PE2, WO_RE0, WO_RE1, WO_RE2,
                             WO_PP, WO_RP, WO_NP0, WO_NP1};
    const int srows[10]   = {19, 128, 128, 56, 128, 128, 256, 384, 128, 128};
    for (int i = 0; i < 10; i++) {
        wa.src[i] = srcs[i]; wa.rowStart[i] = starts[i]; wa.srcRows[i] = srows[i];
    }
    convert_w<<<W_TOTAL_ROWS, 128>>>(wa, wbuf);

    // 1) edge indices from one-hot Rr/Rs  (memory-bound floor)
    extract_idx<<<(2 * BNR * 32 + 255) / 256, 256>>>(Rr, Rs, rr, rs);

    // 2) feature assembly
    build_pin<<<(NODES + 255) / 256, 256>>>(state, attrs, action, pden, phys,
                                            pin_f, pin_h);
    build_rin<<<(BNR + 127) / 128, 128>>>(pin_f, attrs, pinst, rr, rs, rin_h);

    // 3) encoders, particle + relation fused per layer
    enc_k<<<NODES / 64 + BNR / 64, 256>>>(
        pin_h, 32, 32, wbuf + WO_PE0 * 128, pe_b0, t0, nullptr, nullptr, NODES / 64,
        rin_h, 64, 64, wbuf + WO_RE0 * 128, re_b0, r0);
    enc_k<<<NODES / 64 + BNR / 64, 256>>>(
        t0, 128, 128, wbuf + WO_PE1 * 128, pe_b1, t1, nullptr, nullptr, NODES / 64,
        r0, 128, 128, wbuf + WO_RE1 * 128, re_b1, r1);
    // layer 2: particle branch also dups into pEff and zeroes agg
    enc_k<<<NODES / 64 + BNR / 64, 256>>>(
        t1, 128, 128, wbuf + WO_PE2 * 128, pe_b2, pEnc, pEff, agg, NODES / 64,
        r1, 128, 128, wbuf + WO_RE2 * 128, re_b2, relE);

    // 4) propagation: 3 steps (partprop epilogue re-zeroes agg for next step)
    for (int step = 0; step < 3; step++) {
        relprop_k<<<BNR / 64, 256>>>(relE, pEff, wbuf + WO_RP * 128, rp_b,
                                     agg, rr, rs);
        partprop_k<<<NODES / 64, 256>>>(pEnc, agg, wbuf + WO_PP * 128, pp_b,
                                        pEff, agg);
    }

    // 5) head
    enc_k<<<NODES / 64, 256>>>(
        pEff, 128, 128, wbuf + WO_NP0 * 128, np_b0, t0, nullptr, nullptr, NODES / 64,
        nullptr, 128, 128, nullptr, nullptr, nullptr);
    enc_k<<<NODES / 64, 256>>>(
        t0, 128, 128, wbuf + WO_NP1 * 128, np_b1, t1, nullptr, nullptr, NODES / 64,
        nullptr, 128, 128, nullptr, nullptr, nullptr);
    final_k<<<(BB * NP * 32 + 255) / 256, 256>>>(t1, np_W2, np_b2, state, out);
}